// round 13
// baseline (speedup 1.0000x reference)
#include <cuda_runtime.h>
#include <cuda_fp16.h>

#define NN 2048
#define DD 64
#define BH 32
#define BM 128
#define BN 32
#define NKT (NN / BN)

#define QSTR2 36                 // words per row (144 B) — Q stage
#define TSTR  36                 // words per row (144 B) — K and V tiles
#define TBUFW (BN * TSTR)        // 1152 words per tile buffer
#define SMEM_WORDS (4 * TBUFW)   // 18432 B

#define TOTH (BH * NN * DD)

__device__ __align__(16) __half QH[TOTH];   // holds Q * 0.125 (exact exponent shift)
__device__ __align__(16) __half KH[TOTH];
__device__ __align__(16) __half VH[TOTH];

__device__ __forceinline__ unsigned h2(float lo, float hi) {
    __half2 t = __floats2half2_rn(lo, hi);
    return *reinterpret_cast<unsigned*>(&t);
}
__device__ __forceinline__ unsigned tanh_h2(unsigned x) {
    unsigned y; asm("tanh.approx.f16x2 %0, %1;" : "=r"(y) : "r"(x));
    return y;
}
// key permutation (involution) for conflict-free SMEM tiles
__device__ __forceinline__ int prow(int r) {
    return (r & 1) | (((r >> 3) & 3) << 1) | (((r >> 1) & 3) << 3);
}
__device__ __forceinline__ void mma16(float c[4], const unsigned a[4],
                                      unsigned b0, unsigned b1) {
    asm volatile(
        "mma.sync.aligned.m16n8k16.row.col.f32.f16.f16.f32 "
        "{%0,%1,%2,%3}, {%4,%5,%6,%7}, {%8,%9}, {%0,%1,%2,%3};"
        : "+f"(c[0]), "+f"(c[1]), "+f"(c[2]), "+f"(c[3])
        : "r"(a[0]), "r"(a[1]), "r"(a[2]), "r"(a[3]), "r"(b0), "r"(b1));
}
__device__ __forceinline__ void ldsm4(unsigned& r0, unsigned& r1, unsigned& r2,
                                      unsigned& r3, unsigned saddr) {
    asm volatile("ldmatrix.sync.aligned.m8n8.x4.shared.b16 {%0,%1,%2,%3}, [%4];"
                 : "=r"(r0), "=r"(r1), "=r"(r2), "=r"(r3) : "r"(saddr));
}
__device__ __forceinline__ void ldsm4t(unsigned& r0, unsigned& r1, unsigned& r2,
                                       unsigned& r3, unsigned saddr) {
    asm volatile("ldmatrix.sync.aligned.m8n8.x4.trans.shared.b16 {%0,%1,%2,%3}, [%4];"
                 : "=r"(r0), "=r"(r1), "=r"(r2), "=r"(r3) : "r"(saddr));
}
__device__ __forceinline__ void cpa16(unsigned dst, const void* src) {
    asm volatile("cp.async.cg.shared.global [%0], [%1], 16;" :: "r"(dst), "l"(src) : "memory");
}
#define CPA_COMMIT() asm volatile("cp.async.commit_group;" ::: "memory")
#define CPA_WAIT0()  asm volatile("cp.async.wait_group 0;" ::: "memory")

// shuffle-redistribute 4 mask words from line-aligned loaders
__device__ __forceinline__ void mshuf(unsigned out[4], const uint4& a, const uint4& b,
                                      int src, bool pickb) {
    unsigned t0, t1;
    t0 = __shfl_sync(0xffffffffu, a.x, src); t1 = __shfl_sync(0xffffffffu, b.x, src);
    out[0] = pickb ? t1 : t0;
    t0 = __shfl_sync(0xffffffffu, a.y, src); t1 = __shfl_sync(0xffffffffu, b.y, src);
    out[1] = pickb ? t1 : t0;
    t0 = __shfl_sync(0xffffffffu, a.z, src); t1 = __shfl_sync(0xffffffffu, b.z, src);
    out[2] = pickb ? t1 : t0;
    t0 = __shfl_sync(0xffffffffu, a.w, src); t1 = __shfl_sync(0xffffffffu, b.w, src);
    out[3] = pickb ? t1 : t0;
}
// redistribute + pack into fp16x2 AND-masks: zm[nt] zeroes keys 8lt+2nt / +2nt+1
__device__ __forceinline__ void mzm(unsigned zm[4], const uint4& a, const uint4& b,
                                    int s0, int s1, bool pickb) {
    unsigned lo[4], hi[4];
    mshuf(lo, a, b, s0, pickb);   // keys 8lt .. 8lt+3
    mshuf(hi, a, b, s1, pickb);   // keys 8lt+4 .. 8lt+7
    zm[0] = (lo[0] ? 0u : 0xFFFFu) | (lo[1] ? 0u : 0xFFFF0000u);
    zm[1] = (lo[2] ? 0u : 0xFFFFu) | (lo[3] ? 0u : 0xFFFF0000u);
    zm[2] = (hi[0] ? 0u : 0xFFFFu) | (hi[1] ? 0u : 0xFFFF0000u);
    zm[3] = (hi[2] ? 0u : 0xFFFFu) | (hi[3] ? 0u : 0xFFFF0000u);
}

// ---------------- prekernel: fp32 -> fp16 (Q pre-scaled by 0.125) ----------------
__global__ __launch_bounds__(256)
void cvt_f2h_kernel(const float* __restrict__ Q, const float* __restrict__ K,
                    const float* __restrict__ V)
{
    const int i = blockIdx.x * 256 + threadIdx.x;
    {
        float4 a = ((const float4*)Q)[2 * i], b = ((const float4*)Q)[2 * i + 1];
        ((uint4*)QH)[i] = make_uint4(h2(a.x * 0.125f, a.y * 0.125f),
                                     h2(a.z * 0.125f, a.w * 0.125f),
                                     h2(b.x * 0.125f, b.y * 0.125f),
                                     h2(b.z * 0.125f, b.w * 0.125f));
    }
    {
        float4 a = ((const float4*)K)[2 * i], b = ((const float4*)K)[2 * i + 1];
        ((uint4*)KH)[i] = make_uint4(h2(a.x, a.y), h2(a.z, a.w), h2(b.x, b.y), h2(b.z, b.w));
    }
    {
        float4 a = ((const float4*)V)[2 * i], b = ((const float4*)V)[2 * i + 1];
        ((uint4*)VH)[i] = make_uint4(h2(a.x, a.y), h2(a.z, a.w), h2(b.x, b.y), h2(b.z, b.w));
    }
}

// ---------------- main kernel ----------------
__global__ __launch_bounds__(256, 2)
void selfatt_h16z_kernel(const unsigned int* __restrict__ M, float* __restrict__ O)
{
    __shared__ __align__(16) unsigned smem[SMEM_WORDS];

    const int tid  = threadIdx.x;
    const int lane = tid & 31;
    const int w    = tid >> 5;
    const int lg   = lane >> 2;
    const int lt   = lane & 3;
    const int r0   = w * 16;

    const int ln    = lane & 7;
    const int qsel  = (lane >> 4) & 1;
    const int qhalf = (lane >> 3) & 1;
    const unsigned sbase  = (unsigned)__cvta_generic_to_shared(smem);
    const unsigned g1base = (unsigned)((qsel * 8 + ln) * 144 + qhalf * 16);
    const unsigned g2base = (unsigned)((lane & 15) * 144 + ((lane >> 4) & 1) * 16);

    const int sA0 = ((lg & 3) << 3) | (2 * lt);
    const int sA1 = sA0 + 1;
    const bool pkb = (lg & 4) != 0;

    const int bh = blockIdx.y;
    const int q0 = blockIdx.x * BM;

    const __half* qb = QH + (size_t)bh * NN * DD;
    const __half* kb = KH + (size_t)bh * NN * DD;
    const __half* vb = VH + (size_t)bh * NN * DD;
    const unsigned int* mb = M + (size_t)bh * NN * NN;

    const int s_row = tid >> 3;
    const int s_dg  = tid & 7;
    const int s_pr  = prow(s_row);
    const unsigned t_dst = (unsigned)(s_pr * 144 + s_dg * 16);

    // ---- stage Q fp16 (already scaled), pull A-fragments ----
    #pragma unroll
    for (int pass = 0; pass < 4; pass++) {
        int r = pass * 32 + s_row;
        *(uint4*)(smem + r * QSTR2 + s_dg * 4) =
            *(const uint4*)(qb + (size_t)(q0 + r) * DD + s_dg * 8);
    }
    __syncthreads();
    unsigned qa[4][4];
    #pragma unroll
    for (int kb16 = 0; kb16 < 4; kb16++) {
        const unsigned* p0 = smem + (r0 + lg) * QSTR2 + kb16 * 8;
        const unsigned* p8 = p0 + 8 * QSTR2;
        qa[kb16][0] = p0[lt];     qa[kb16][1] = p8[lt];
        qa[kb16][2] = p0[lt + 4]; qa[kb16][3] = p8[lt + 4];
    }
    __syncthreads();

    // ---- cp.async stage K(0)->Kbuf0, K(1)->Kbuf1, V(0)->Vbuf0 ----
    cpa16(sbase + 0 * (TBUFW * 4) + t_dst, kb + (size_t)s_row * DD + s_dg * 8);
    cpa16(sbase + 1 * (TBUFW * 4) + t_dst, kb + (size_t)(BN + s_row) * DD + s_dg * 8);
    cpa16(sbase + 2 * (TBUFW * 4) + t_dst, vb + (size_t)s_row * DD + s_dg * 8);
    CPA_COMMIT();

    // ---- mask tile 0 ----
    const unsigned int* mwbase = mb + (size_t)(q0 + r0) * NN;
    uint4 mr0, mr1, mr2, mr3;
    {
        const size_t rrow = (size_t)((lane >> 3)) * NN + 4 * (lane & 7);
        mr0 = *(const uint4*)(mwbase + rrow);
        mr1 = *(const uint4*)(mwbase + 4 * (size_t)NN + rrow);
        mr2 = *(const uint4*)(mwbase + 8 * (size_t)NN + rrow);
        mr3 = *(const uint4*)(mwbase + 12 * (size_t)NN + rrow);
    }
    unsigned zma[4], zmb[4];
    mzm(zma, mr0, mr1, sA0, sA1, pkb);
    mzm(zmb, mr2, mr3, sA0, sA1, pkb);

    CPA_WAIT0();
    __syncthreads();

    float oacc[8][4];
    #pragma unroll
    for (int nt = 0; nt < 8; nt++)
        #pragma unroll
        for (int i = 0; i < 4; i++) oacc[nt][i] = 0.0f;

    // ---- pre-loop GEMM1(0) ----
    float sc[4][4];
    #pragma unroll
    for (int nt = 0; nt < 4; nt++)
        #pragma unroll
        for (int i = 0; i < 4; i++) sc[nt][i] = 0.0f;
    #pragma unroll
    for (int kb16 = 0; kb16 < 4; kb16++)
        #pragma unroll
        for (int ntp = 0; ntp < 2; ntp++) {
            unsigned b0, b1, b2, b3;
            ldsm4(b0, b1, b2, b3, sbase + g1base + ntp * 2304 + kb16 * 32);
            mma16(sc[ntp * 2 + 0], qa[kb16], b0, b1);
            mma16(sc[ntp * 2 + 1], qa[kb16], b2, b3);
        }
    __syncthreads();

    for (int it = 0; it < NKT; it++) {
        const bool hasN1 = (it + 1 < NKT);
        const bool hasN2 = (it + 2 < NKT);

        // ---- cp.async next tiles ----
        if (hasN2)
            cpa16(sbase + (unsigned)((it & 1)) * (TBUFW * 4) + t_dst,
                  kb + (size_t)((it + 2) * BN + s_row) * DD + s_dg * 8);
        if (hasN1)
            cpa16(sbase + (unsigned)(2 + ((it + 1) & 1)) * (TBUFW * 4) + t_dst,
                  vb + (size_t)((it + 1) * BN + s_row) * DD + s_dg * 8);
        CPA_COMMIT();

        // ---- raw mask loads for tile it+1 ----
        if (hasN1) {
            const size_t rrow = (size_t)((lane >> 3)) * NN + (it + 1) * BN + 4 * (lane & 7);
            mr0 = *(const uint4*)(mwbase + rrow);
            mr1 = *(const uint4*)(mwbase + 4 * (size_t)NN + rrow);
            mr2 = *(const uint4*)(mwbase + 8 * (size_t)NN + rrow);
            mr3 = *(const uint4*)(mwbase + 12 * (size_t)NN + rrow);
        }

        // ---- S(it): cvt -> tanh.f16x2 -> AND mask (scores pre-scaled via Q) ----
        unsigned aS[2][4];
        #pragma unroll
        for (int kb2 = 0; kb2 < 2; kb2++) {
            const int n0 = 2 * kb2, n1 = 2 * kb2 + 1;
            aS[kb2][0] = tanh_h2(h2(sc[n0][0], sc[n0][1])) & zma[n0];
            aS[kb2][1] = tanh_h2(h2(sc[n0][2], sc[n0][3])) & zmb[n0];
            aS[kb2][2] = tanh_h2(h2(sc[n1][0], sc[n1][1])) & zma[n1];
            aS[kb2][3] = tanh_h2(h2(sc[n1][2], sc[n1][3])) & zmb[n1];
        }

        // ---- GEMM1(it+1): refill sc ----
        if (hasN1) {
            #pragma unroll
            for (int nt = 0; nt < 4; nt++)
                #pragma unroll
                for (int i = 0; i < 4; i++) sc[nt][i] = 0.0f;
            const unsigned kB = sbase + ((unsigned)((it + 1) & 1)) * (TBUFW * 4) + g1base;
            #pragma unroll
            for (int kb16 = 0; kb16 < 4; kb16++)
                #pragma unroll
                for (int ntp = 0; ntp < 2; ntp++) {
                    unsigned b0, b1, b2, b3;
                    ldsm4(b0, b1, b2, b3, kB + ntp * 2304 + kb16 * 32);
                    mma16(sc[ntp * 2 + 0], qa[kb16], b0, b1);
                    mma16(sc[ntp * 2 + 1], qa[kb16], b2, b3);
                }
        }

        // ---- GEMM2(it) ----
        {
            const unsigned vB = sbase + (unsigned)(2 * TBUFW * 4)
                              + ((unsigned)(it & 1)) * (TBUFW * 4) + g2base;
            #pragma unroll
            for (int kb2 = 0; kb2 < 2; kb2++)
                #pragma unroll
                for (int ntp = 0; ntp < 4; ntp++) {
                    unsigned b0, b1, b2, b3;
                    ldsm4t(b0, b1, b2, b3, vB + kb2 * 2304 + ntp * 32);
                    mma16(oacc[ntp * 2 + 0], aS[kb2], b0, b1);
                    mma16(oacc[ntp * 2 + 1], aS[kb2], b2, b3);
                }
        }

        // ---- next mask tile -> packed AND masks ----
        if (hasN1) {
            mzm(zma, mr0, mr1, sA0, sA1, pkb);
            mzm(zmb, mr2, mr3, sA0, sA1, pkb);
        }

        CPA_WAIT0();
        __syncthreads();
    }

    // ---- epilogue ----
    #pragma unroll
    for (int nt = 0; nt < 8; nt++) {
        float* o0 = O + ((size_t)bh * NN + q0 + r0 + lg) * DD + nt * 8 + 2 * lt;
        *(float2*)o0            = make_float2(oacc[nt][0], oacc[nt][1]);
        *(float2*)(o0 + 8 * DD) = make_float2(oacc[nt][2], oacc[nt][3]);
    }
}

extern "C" void kernel_launch(void* const* d_in, const int* in_sizes, int n_in,
                              void* d_out, int out_size)
{
    const float* q = (const float*)d_in[0];
    const float* k = (const float*)d_in[1];
    const float* v = (const float*)d_in[2];
    const unsigned int* m = (const unsigned int*)d_in[3];
    float* o = (float*)d_out;

    cvt_f2h_kernel<<<TOTH / 8 / 256, 256>>>(q, k, v);
    dim3 grid(NN / BM, BH);
    selfatt_h16z_kernel<<<grid, 256>>>(m, o);
}

// round 14
// speedup vs baseline: 1.0892x; 1.0892x over previous
#include <cuda_runtime.h>
#include <cuda_fp16.h>

#define NN 2048
#define DD 64
#define BH 32
#define BM 128
#define BN 32
#define NKT (NN / BN)

#define QSTR2 36                 // words per row (144 B) — Q stage
#define TSTR  36                 // words per row (144 B) — K and V tiles
#define TBUFW (BN * TSTR)        // 1152 words per tile buffer
#define SMEM_WORDS (4 * TBUFW)   // 18432 B

#define TOTH (BH * NN * DD)

__device__ __align__(16) __half QH[TOTH];   // holds Q * 0.125 (exact exponent shift)
__device__ __align__(16) __half KH[TOTH];
__device__ __align__(16) __half VH[TOTH];

__device__ __forceinline__ float tanh_fast(float x) {
    float y; asm("tanh.approx.f32 %0, %1;" : "=f"(y) : "f"(x));
    return y;
}
__device__ __forceinline__ unsigned h2(float lo, float hi) {
    __half2 t = __floats2half2_rn(lo, hi);
    return *reinterpret_cast<unsigned*>(&t);
}
// key permutation (involution) for conflict-free SMEM tiles
__device__ __forceinline__ int prow(int r) {
    return (r & 1) | (((r >> 3) & 3) << 1) | (((r >> 1) & 3) << 3);
}
__device__ __forceinline__ void mma16(float c[4], const unsigned a[4],
                                      unsigned b0, unsigned b1) {
    asm volatile(
        "mma.sync.aligned.m16n8k16.row.col.f32.f16.f16.f32 "
        "{%0,%1,%2,%3}, {%4,%5,%6,%7}, {%8,%9}, {%0,%1,%2,%3};"
        : "+f"(c[0]), "+f"(c[1]), "+f"(c[2]), "+f"(c[3])
        : "r"(a[0]), "r"(a[1]), "r"(a[2]), "r"(a[3]), "r"(b0), "r"(b1));
}
__device__ __forceinline__ void ldsm4(unsigned& r0, unsigned& r1, unsigned& r2,
                                      unsigned& r3, unsigned saddr) {
    asm volatile("ldmatrix.sync.aligned.m8n8.x4.shared.b16 {%0,%1,%2,%3}, [%4];"
                 : "=r"(r0), "=r"(r1), "=r"(r2), "=r"(r3) : "r"(saddr));
}
__device__ __forceinline__ void ldsm4t(unsigned& r0, unsigned& r1, unsigned& r2,
                                       unsigned& r3, unsigned saddr) {
    asm volatile("ldmatrix.sync.aligned.m8n8.x4.trans.shared.b16 {%0,%1,%2,%3}, [%4];"
                 : "=r"(r0), "=r"(r1), "=r"(r2), "=r"(r3) : "r"(saddr));
}
__device__ __forceinline__ void cpa16(unsigned dst, const void* src) {
    asm volatile("cp.async.cg.shared.global [%0], [%1], 16;" :: "r"(dst), "l"(src) : "memory");
}
#define CPA_COMMIT() asm volatile("cp.async.commit_group;" ::: "memory")
#define CPA_WAIT0()  asm volatile("cp.async.wait_group 0;" ::: "memory")

// shuffle-redistribute one uint4-worth of mask words from line-aligned loaders
__device__ __forceinline__ void mshuf(unsigned out[4], const uint4& a, const uint4& b,
                                      int src, bool pickb) {
    unsigned t0, t1;
    t0 = __shfl_sync(0xffffffffu, a.x, src); t1 = __shfl_sync(0xffffffffu, b.x, src);
    out[0] = pickb ? t1 : t0;
    t0 = __shfl_sync(0xffffffffu, a.y, src); t1 = __shfl_sync(0xffffffffu, b.y, src);
    out[1] = pickb ? t1 : t0;
    t0 = __shfl_sync(0xffffffffu, a.z, src); t1 = __shfl_sync(0xffffffffu, b.z, src);
    out[2] = pickb ? t1 : t0;
    t0 = __shfl_sync(0xffffffffu, a.w, src); t1 = __shfl_sync(0xffffffffu, b.w, src);
    out[3] = pickb ? t1 : t0;
}

// ---------------- prekernel: fp32 -> fp16 (Q pre-scaled by 0.125) ----------------
__global__ __launch_bounds__(256)
void cvt_f2h_kernel(const float* __restrict__ Q, const float* __restrict__ K,
                    const float* __restrict__ V)
{
    const int i = blockIdx.x * 256 + threadIdx.x;   // 0 .. TOTH/8-1
    {
        float4 a = ((const float4*)Q)[2 * i], b = ((const float4*)Q)[2 * i + 1];
        ((uint4*)QH)[i] = make_uint4(h2(a.x * 0.125f, a.y * 0.125f),
                                     h2(a.z * 0.125f, a.w * 0.125f),
                                     h2(b.x * 0.125f, b.y * 0.125f),
                                     h2(b.z * 0.125f, b.w * 0.125f));
    }
    {
        float4 a = ((const float4*)K)[2 * i], b = ((const float4*)K)[2 * i + 1];
        ((uint4*)KH)[i] = make_uint4(h2(a.x, a.y), h2(a.z, a.w), h2(b.x, b.y), h2(b.z, b.w));
    }
    {
        float4 a = ((const float4*)V)[2 * i], b = ((const float4*)V)[2 * i + 1];
        ((uint4*)VH)[i] = make_uint4(h2(a.x, a.y), h2(a.z, a.w), h2(b.x, b.y), h2(b.z, b.w));
    }
}

// ---------------- main kernel ----------------
__global__ __launch_bounds__(256, 2)
void selfatt_h16s_kernel(const unsigned int* __restrict__ M, float* __restrict__ O)
{
    __shared__ __align__(16) unsigned smem[SMEM_WORDS];

    const int tid  = threadIdx.x;
    const int lane = tid & 31;
    const int w    = tid >> 5;
    const int lg   = lane >> 2;
    const int lt   = lane & 3;
    const int r0   = w * 16;

    // LDSM lane-constant byte offsets (tile stride 144 B)
    const int ln    = lane & 7;
    const int qsel  = (lane >> 4) & 1;
    const int qhalf = (lane >> 3) & 1;
    const unsigned sbase  = (unsigned)__cvta_generic_to_shared(smem);
    const unsigned g1base = (unsigned)((qsel * 8 + ln) * 144 + qhalf * 16);         // K (non-trans)
    const unsigned g2base = (unsigned)((lane & 15) * 144 + ((lane >> 4) & 1) * 16); // V (trans)

    // mask shuffle sources
    const int sA0 = ((lg & 3) << 3) | (2 * lt);
    const int sA1 = sA0 + 1;
    const bool pkb = (lg & 4) != 0;

    const int bh = blockIdx.y;
    const int q0 = blockIdx.x * BM;

    const __half* qb = QH + (size_t)bh * NN * DD;
    const __half* kb = KH + (size_t)bh * NN * DD;
    const __half* vb = VH + (size_t)bh * NN * DD;
    const unsigned int* mb = M + (size_t)bh * NN * NN;

    const int s_row = tid >> 3;          // key within tile
    const int s_dg  = tid & 7;           // 16B chunk within 128B row
    const int s_pr  = prow(s_row);       // permuted SMEM row
    const unsigned t_dst = (unsigned)(s_pr * 144 + s_dg * 16);

    // ---- stage Q fp16 (pre-scaled, direct copy), pull A-fragments ----
    #pragma unroll
    for (int pass = 0; pass < 4; pass++) {
        int r = pass * 32 + s_row;
        *(uint4*)(smem + r * QSTR2 + s_dg * 4) =
            *(const uint4*)(qb + (size_t)(q0 + r) * DD + s_dg * 8);
    }
    __syncthreads();
    unsigned qa[4][4];
    #pragma unroll
    for (int kb16 = 0; kb16 < 4; kb16++) {
        const unsigned* p0 = smem + (r0 + lg) * QSTR2 + kb16 * 8;
        const unsigned* p8 = p0 + 8 * QSTR2;
        qa[kb16][0] = p0[lt];     qa[kb16][1] = p8[lt];
        qa[kb16][2] = p0[lt + 4]; qa[kb16][3] = p8[lt + 4];
    }
    __syncthreads();   // Q stage dead -> tile buffers

    // ---- cp.async stage K(0)->Kbuf0, K(1)->Kbuf1, V(0)->Vbuf0 ----
    cpa16(sbase + 0 * (TBUFW * 4) + t_dst, kb + (size_t)s_row * DD + s_dg * 8);
    cpa16(sbase + 1 * (TBUFW * 4) + t_dst, kb + (size_t)(BN + s_row) * DD + s_dg * 8);
    cpa16(sbase + 2 * (TBUFW * 4) + t_dst, vb + (size_t)s_row * DD + s_dg * 8);
    CPA_COMMIT();

    // ---- mask tile 0: line-aligned raw loads + shuffle redistribute ----
    const unsigned int* mwbase = mb + (size_t)(q0 + r0) * NN;
    uint4 mr0, mr1, mr2, mr3;
    {
        const size_t rrow = (size_t)((lane >> 3)) * NN + 4 * (lane & 7);
        mr0 = *(const uint4*)(mwbase + rrow);
        mr1 = *(const uint4*)(mwbase + 4 * (size_t)NN + rrow);
        mr2 = *(const uint4*)(mwbase + 8 * (size_t)NN + rrow);
        mr3 = *(const uint4*)(mwbase + 12 * (size_t)NN + rrow);
    }
    unsigned mka[8], mkb[8];
    mshuf(&mka[0], mr0, mr1, sA0, pkb);
    mshuf(&mka[4], mr0, mr1, sA1, pkb);
    mshuf(&mkb[0], mr2, mr3, sA0, pkb);
    mshuf(&mkb[4], mr2, mr3, sA1, pkb);

    CPA_WAIT0();
    __syncthreads();

    float oacc[8][4];
    #pragma unroll
    for (int nt = 0; nt < 8; nt++)
        #pragma unroll
        for (int i = 0; i < 4; i++) oacc[nt][i] = 0.0f;

    // ---- pre-loop GEMM1(0) from Kbuf0 ----
    float sc[4][4];
    #pragma unroll
    for (int nt = 0; nt < 4; nt++)
        #pragma unroll
        for (int i = 0; i < 4; i++) sc[nt][i] = 0.0f;
    #pragma unroll
    for (int kb16 = 0; kb16 < 4; kb16++)
        #pragma unroll
        for (int ntp = 0; ntp < 2; ntp++) {
            unsigned b0, b1, b2, b3;
            ldsm4(b0, b1, b2, b3, sbase + g1base + ntp * 2304 + kb16 * 32);
            mma16(sc[ntp * 2 + 0], qa[kb16], b0, b1);
            mma16(sc[ntp * 2 + 1], qa[kb16], b2, b3);
        }
    __syncthreads();

    for (int it = 0; it < NKT; it++) {
        const bool hasN1 = (it + 1 < NKT);
        const bool hasN2 = (it + 2 < NKT);

        // ---- cp.async: K(it+2)->Kbuf[it&1], V(it+1)->Vbuf[(it+1)&1] ----
        if (hasN2)
            cpa16(sbase + (unsigned)((it & 1)) * (TBUFW * 4) + t_dst,
                  kb + (size_t)((it + 2) * BN + s_row) * DD + s_dg * 8);
        if (hasN1)
            cpa16(sbase + (unsigned)(2 + ((it + 1) & 1)) * (TBUFW * 4) + t_dst,
                  vb + (size_t)((it + 1) * BN + s_row) * DD + s_dg * 8);
        CPA_COMMIT();

        // ---- raw mask loads for tile it+1 (line-aligned) ----
        if (hasN1) {
            const size_t rrow = (size_t)((lane >> 3)) * NN + (it + 1) * BN + 4 * (lane & 7);
            mr0 = *(const uint4*)(mwbase + rrow);
            mr1 = *(const uint4*)(mwbase + 4 * (size_t)NN + rrow);
            mr2 = *(const uint4*)(mwbase + 8 * (size_t)NN + rrow);
            mr3 = *(const uint4*)(mwbase + 12 * (size_t)NN + rrow);
        }

        // ---- tanh + mask + pack S(it) (scores pre-scaled via Q) ----
        unsigned aS[2][4];
        #pragma unroll
        for (int kb2 = 0; kb2 < 2; kb2++) {
            {
                const int nt = 2 * kb2;
                float w0 = mka[2 * nt]     ? 0.0f : tanh_fast(sc[nt][0]);
                float w1 = mka[2 * nt + 1] ? 0.0f : tanh_fast(sc[nt][1]);
                float w2 = mkb[2 * nt]     ? 0.0f : tanh_fast(sc[nt][2]);
                float w3 = mkb[2 * nt + 1] ? 0.0f : tanh_fast(sc[nt][3]);
                aS[kb2][0] = h2(w0, w1);
                aS[kb2][1] = h2(w2, w3);
            }
            {
                const int nt = 2 * kb2 + 1;
                float w0 = mka[2 * nt]     ? 0.0f : tanh_fast(sc[nt][0]);
                float w1 = mka[2 * nt + 1] ? 0.0f : tanh_fast(sc[nt][1]);
                float w2 = mkb[2 * nt]     ? 0.0f : tanh_fast(sc[nt][2]);
                float w3 = mkb[2 * nt + 1] ? 0.0f : tanh_fast(sc[nt][3]);
                aS[kb2][2] = h2(w0, w1);
                aS[kb2][3] = h2(w2, w3);
            }
        }

        // ---- GEMM1(it+1): refill sc from Kbuf (it+1)&1 ----
        if (hasN1) {
            #pragma unroll
            for (int nt = 0; nt < 4; nt++)
                #pragma unroll
                for (int i = 0; i < 4; i++) sc[nt][i] = 0.0f;
            const unsigned kB = sbase + ((unsigned)((it + 1) & 1)) * (TBUFW * 4) + g1base;
            #pragma unroll
            for (int kb16 = 0; kb16 < 4; kb16++)
                #pragma unroll
                for (int ntp = 0; ntp < 2; ntp++) {
                    unsigned b0, b1, b2, b3;
                    ldsm4(b0, b1, b2, b3, kB + ntp * 2304 + kb16 * 32);
                    mma16(sc[ntp * 2 + 0], qa[kb16], b0, b1);
                    mma16(sc[ntp * 2 + 1], qa[kb16], b2, b3);
                }
        }

        // ---- GEMM2(it): oacc += S . V from Vbuf it&1 ----
        {
            const unsigned vB = sbase + (unsigned)(2 * TBUFW * 4)
                              + ((unsigned)(it & 1)) * (TBUFW * 4) + g2base;
            #pragma unroll
            for (int kb2 = 0; kb2 < 2; kb2++)
                #pragma unroll
                for (int ntp = 0; ntp < 4; ntp++) {
                    unsigned b0, b1, b2, b3;
                    ldsm4t(b0, b1, b2, b3, vB + kb2 * 2304 + ntp * 32);
                    mma16(oacc[ntp * 2 + 0], aS[kb2], b0, b1);
                    mma16(oacc[ntp * 2 + 1], aS[kb2], b2, b3);
                }
        }

        // ---- redistribute next mask tile ----
        if (hasN1) {
            mshuf(&mka[0], mr0, mr1, sA0, pkb);
            mshuf(&mka[4], mr0, mr1, sA1, pkb);
            mshuf(&mkb[0], mr2, mr3, sA0, pkb);
            mshuf(&mkb[4], mr2, mr3, sA1, pkb);
        }

        CPA_WAIT0();
        __syncthreads();
    }

    // ---- epilogue ----
    #pragma unroll
    for (int nt = 0; nt < 8; nt++) {
        float* o0 = O + ((size_t)bh * NN + q0 + r0 + lg) * DD + nt * 8 + 2 * lt;
        *(float2*)o0            = make_float2(oacc[nt][0], oacc[nt][1]);
        *(float2*)(o0 + 8 * DD) = make_float2(oacc[nt][2], oacc[nt][3]);
    }
}

extern "C" void kernel_launch(void* const* d_in, const int* in_sizes, int n_in,
                              void* d_out, int out_size)
{
    const float* q = (const float*)d_in[0];
    const float* k = (const float*)d_in[1];
    const float* v = (const float*)d_in[2];
    const unsigned int* m = (const unsigned int*)d_in[3];
    float* o = (float*)d_out;

    cvt_f2h_kernel<<<TOTH / 8 / 256, 256>>>(q, k, v);
    dim3 grid(NN / BM, BH);
    selfatt_h16s_kernel<<<grid, 256>>>(m, o);
}